// round 9
// baseline (speedup 1.0000x reference)
#include <cuda_runtime.h>
#include <cooperative_groups.h>

namespace cg = cooperative_groups;

// Problem constants (fixed by the reference)
#define BATCH 128
#define TSTEPS 2048
#define INDIM 32
#define HDIM 256
#define LDIM 16

#define CLS 8          // cluster size = CTAs per batch-group
#define TB 256         // threads per CTA (8 warps)

struct Smem {
    float hbuf[2][2][8][4][32];   // [chain][buf][src rank][batch][lane]  16KB
    float4 scratch[2][8][4][32];  // [chain][kchunk][batch][col]          32KB
    float xbuf[2][2][4][32];      // [chain][buf][batch][dim]              2KB
    unsigned long long mbars[4];  // [chain][buf]
};
#define SMEM_BYTES ((int)sizeof(Smem))

__device__ __forceinline__ unsigned long long pk2(float lo, float hi) {
    return ((unsigned long long)__float_as_uint(hi) << 32) |
           (unsigned long long)__float_as_uint(lo);
}
__device__ __forceinline__ float sum2(unsigned long long v) {
    return __uint_as_float((unsigned int)v) +
           __uint_as_float((unsigned int)(v >> 32));
}
#define FMA2(acc, w, h) \
    asm("fma.rn.f32x2 %0, %1, %2, %0;" : "+l"(acc) : "l"(w), "l"(h))

__device__ __forceinline__ unsigned smem_u32(const void* p) {
    unsigned r;
    asm("{ .reg .u64 t; cvta.to.shared.u64 t, %1; cvt.u32.u64 %0, t; }"
        : "=r"(r) : "l"(p));
    return r;
}

__device__ __forceinline__ float fast_sigmoid(float x) {
    return __fdividef(1.0f, 1.0f + __expf(-x));
}
__device__ __forceinline__ float fast_tanh(float x) {
    float ex = __expf(2.0f * x);
    return fmaf(-2.0f, __fdividef(1.0f, ex + 1.0f), 1.0f);
}

__device__ __forceinline__ void mbar_wait(unsigned addr, unsigned parity) {
    asm volatile(
        "{\n\t"
        ".reg .pred P;\n\t"
        "WL_%=:\n\t"
        "mbarrier.try_wait.parity.acquire.cta.shared::cta.b64 P, [%0], %1, 0x989680;\n\t"
        "@P bra.uni WD_%=;\n\t"
        "bra.uni WL_%=;\n\t"
        "WD_%=:\n\t"
        "}"
        :: "r"(addr), "r"(parity) : "memory");
}

// Matvec partials for one chain: thread = (col=lane, kchunk=warp), 4 batches.
// hb: [8][4][32] floats, xb: [4][32] floats, sc: [8][4][32] float4.
__device__ __forceinline__ void fma_phase(
    const float* __restrict__ hb, const float* __restrict__ xb,
    float4* __restrict__ sc,
    const unsigned long long (*__restrict__ wd)[16],
    const unsigned long long (*__restrict__ wi)[2],
    int warp, int lane)
{
    unsigned long long aR[4], aZ[4], aNh[4], aNi[4];
#pragma unroll
    for (int b = 0; b < 4; b++) { aR[b] = 0ull; aZ[b] = 0ull; aNh[b] = 0ull; aNi[b] = 0ull; }

#pragma unroll
    for (int b = 0; b < 4; b++) {
        ulonglong2 x2 = *reinterpret_cast<const ulonglong2*>(xb + b * 32 + warp * 4);
        FMA2(aR[b],  wi[0][0], x2.x); FMA2(aR[b],  wi[0][1], x2.y);
        FMA2(aZ[b],  wi[1][0], x2.x); FMA2(aZ[b],  wi[1][1], x2.y);
        FMA2(aNi[b], wi[2][0], x2.x); FMA2(aNi[b], wi[2][1], x2.y);
    }
#pragma unroll
    for (int i = 0; i < 8; i++) {
#pragma unroll
        for (int b = 0; b < 4; b++) {
            // broadcast LDS.128: all lanes read the same 16B
            ulonglong2 h2 = *reinterpret_cast<const ulonglong2*>(
                hb + warp * 128 + b * 32 + 4 * i);
            FMA2(aR[b],  wd[0][2 * i],     h2.x);
            FMA2(aR[b],  wd[0][2 * i + 1], h2.y);
            FMA2(aZ[b],  wd[1][2 * i],     h2.x);
            FMA2(aZ[b],  wd[1][2 * i + 1], h2.y);
            FMA2(aNh[b], wd[2][2 * i],     h2.x);
            FMA2(aNh[b], wd[2][2 * i + 1], h2.y);
        }
    }
#pragma unroll
    for (int b = 0; b < 4; b++)
        sc[(warp * 4 + b) * 32 + lane] =
            make_float4(sum2(aR[b]), sum2(aZ[b]), sum2(aNh[b]), sum2(aNi[b]));
}

__global__ void __cluster_dims__(CLS, 1, 1) __launch_bounds__(TB, 1)
gru_persistent_kernel(const float* __restrict__ xg,      // [B,T,IN]
                      const float* __restrict__ xl,      // [B,T,L]
                      const float* __restrict__ h0,      // [B,H]
                      const float* __restrict__ Wih,     // [3H,IN]
                      const float* __restrict__ Whh,     // [3H,H]
                      const float* __restrict__ bias,    // [3H]
                      const float* __restrict__ bias_n,  // [H]
                      float* __restrict__ out)           // [B,T,1]
{
    extern __shared__ __align__(16) char dynsmem[];
    Smem& sm = *reinterpret_cast<Smem*>(dynsmem);

    cg::cluster_group cluster = cg::this_cluster();
    const int rank = (int)cluster.block_rank();     // owns cols [32r, 32r+32)
    const int cid  = blockIdx.x / CLS;              // owns batches [8c, 8c+8)
    const int B0   = cid * 8;
    const int tid  = threadIdx.x;
    const int lane = tid & 31;
    const int warp = tid >> 5;      // FMA: k-chunk (= src rank); gates: batch = warp
    const int col  = rank * 32 + lane;
    const int chain = warp >> 2;    // this warp's gate-phase chain (P=0, Q=1)
    const int wloc  = warp & 3;     // batch within chain

    // ---- Weights in registers, packed (even k, odd k) — shared by both chains ----
    unsigned long long wd[3][16];   // Whh[g][col][warp*32 .. +31]
    unsigned long long wi[3][2];    // Wih[g][col][warp*4 .. +3]
#pragma unroll
    for (int g = 0; g < 3; g++) {
        const float* wr = Whh + (size_t)(g * HDIM + col) * HDIM + warp * 32;
#pragma unroll
        for (int p = 0; p < 16; p++) wd[g][p] = pk2(wr[2 * p], wr[2 * p + 1]);
        const float* wx = Wih + (size_t)(g * HDIM + col) * INDIM + warp * 4;
        wi[g][0] = pk2(wx[0], wx[1]);
        wi[g][1] = pk2(wx[2], wx[3]);
    }
    const float b_r  = bias[col];
    const float b_z  = bias[HDIM + col];
    const float b_ni = bias[2 * HDIM + col];
    const float b_n2 = bias_n[col];

    const unsigned base  = smem_u32(&sm);
    const unsigned hoff  = smem_u32(&sm.hbuf[0][0][0][0][0]) - base;
    const unsigned mboff = smem_u32(&sm.mbars[0]) - base;
    const unsigned mloc  = base + mboff;

    if (tid == 0) {
#pragma unroll
        for (int i = 0; i < 4; i++)
            asm volatile("mbarrier.init.shared.b64 [%0], 1;"
                         :: "r"(mloc + i * 8) : "memory");
    }

    // ---- Init buffer 0 of both chains with h0: [chain][src][batch][lane] ----
    for (int idx = tid; idx < 2 * 8 * 4 * 32; idx += TB) {
        int c = idx >> 10, src = (idx >> 7) & 7, b = (idx >> 5) & 3, l = idx & 31;
        sm.hbuf[c][0][src][b][l] = h0[(size_t)(B0 + c * 4 + b) * HDIM + src * 32 + l];
    }
    sm.xbuf[chain][0][wloc][lane] = xg[(size_t)(B0 + warp) * TSTEPS * INDIM + lane];

    float hreg = h0[(size_t)(B0 + warp) * HDIM + col];   // h_prev (batch B0+warp, col)
    float xl_reg = 0.f;
    if (rank == 0 && lane < LDIM)
        xl_reg = xl[(size_t)(B0 + warp) * TSTEPS * LDIM + lane];

    __syncthreads();
    cluster.sync();    // peers' mbarriers initialized before any bulk copy lands

    if (tid == 0) {
#pragma unroll
        for (int c = 0; c < 2; c++) {
            // complete [c][0] phase 0 (buffer 0 pre-filled locally)
            asm volatile("mbarrier.arrive.shared.b64 _, [%0];"
                         :: "r"(mloc + c * 16) : "memory");
            // arm [c][1] for step 1: 8 src x 4 rows x 128B
            asm volatile("mbarrier.arrive.expect_tx.shared.b64 _, [%0], %1;"
                         :: "r"(mloc + c * 16 + 8), "r"(4096u) : "memory");
        }
    }

    // Per-thread send target (lane 0..7 -> rank 'lane', incl. self)
    unsigned peer = 0;
    {
        int tgt = lane & 7;
        asm("mapa.shared::cluster.u32 %0, %1, %2;" : "=r"(peer) : "r"(base), "r"(tgt));
    }

    for (int t = 0; t < TSTEPS; t++) {
        const int buf = t & 1;
        const unsigned par = (unsigned)((t >> 1) & 1);
        const int tn = (t + 1 < TSTEPS) ? t + 1 : t;

        float xnext = xg[(size_t)(B0 + warp) * TSTEPS * INDIM +
                         (size_t)tn * INDIM + lane];

        // ================= chain P =================
        mbar_wait(mloc + (unsigned)(buf * 8), par);
        if (tid == 0 && t + 2 < TSTEPS)
            asm volatile("mbarrier.arrive.expect_tx.shared.b64 _, [%0], %1;"
                         :: "r"(mloc + (unsigned)(buf * 8)), "r"(4096u) : "memory");

        fma_phase(&sm.hbuf[0][buf][0][0][0], &sm.xbuf[0][buf][0][0],
                  &sm.scratch[0][0][0][0], wd, wi, warp, lane);
        if (chain == 0) sm.xbuf[0][buf ^ 1][wloc][lane] = xnext;

        __syncthreads();   // S1a

        if (chain == 0) {
            float sR = 0.f, sZ = 0.f, sNh = 0.f, sNi = 0.f;
#pragma unroll
            for (int kc = 0; kc < 8; kc++) {
                float4 v = sm.scratch[0][kc][wloc][lane];
                sR += v.x; sZ += v.y; sNh += v.z; sNi += v.w;
            }
            const float r = fast_sigmoid(sR + b_r);
            const float z = fast_sigmoid(sZ + b_z);
            const float n = fast_tanh(sNi + b_ni + r * (sNh + b_n2));
            hreg = n + z * (hreg - n);

            if (t + 1 < TSTEPS) {
                sm.hbuf[0][buf ^ 1][rank][wloc][lane] = hreg;   // stage 128B row
                __syncwarp();
                asm volatile("fence.proxy.async.shared::cta;" ::: "memory");
                if (lane < 8) {
                    const unsigned off = hoff +
                        (unsigned)((buf ^ 1) * 4096 + rank * 512 + wloc * 128);
                    asm volatile(
                        "cp.async.bulk.shared::cluster.shared::cta.mbarrier::complete_tx::bytes "
                        "[%0], [%1], %2, [%3];"
                        :: "r"(peer + off), "r"(base + off), "r"(128u),
                           "r"(peer + mboff + (unsigned)((buf ^ 1) * 8)) : "memory");
                }
            }
            if (rank == 0) {
                float prod = (lane < LDIM) ? hreg * xl_reg : 0.f;
#pragma unroll
                for (int o = 16; o; o >>= 1)
                    prod += __shfl_xor_sync(0xffffffffu, prod, o);
                if (lane == 0) out[(size_t)(B0 + warp) * TSTEPS + t] = prod;
                if (lane < LDIM)
                    xl_reg = xl[(size_t)(B0 + warp) * TSTEPS * LDIM +
                                (size_t)tn * LDIM + lane];
            }
        }

        // ================= chain Q =================
        mbar_wait(mloc + (unsigned)(16 + buf * 8), par);
        if (tid == 0 && t + 2 < TSTEPS)
            asm volatile("mbarrier.arrive.expect_tx.shared.b64 _, [%0], %1;"
                         :: "r"(mloc + (unsigned)(16 + buf * 8)), "r"(4096u) : "memory");

        fma_phase(&sm.hbuf[1][buf][0][0][0], &sm.xbuf[1][buf][0][0],
                  &sm.scratch[1][0][0][0], wd, wi, warp, lane);
        if (chain == 1) sm.xbuf[1][buf ^ 1][wloc][lane] = xnext;

        __syncthreads();   // S1b

        if (chain == 1) {
            float sR = 0.f, sZ = 0.f, sNh = 0.f, sNi = 0.f;
#pragma unroll
            for (int kc = 0; kc < 8; kc++) {
                float4 v = sm.scratch[1][kc][wloc][lane];
                sR += v.x; sZ += v.y; sNh += v.z; sNi += v.w;
            }
            const float r = fast_sigmoid(sR + b_r);
            const float z = fast_sigmoid(sZ + b_z);
            const float n = fast_tanh(sNi + b_ni + r * (sNh + b_n2));
            hreg = n + z * (hreg - n);

            if (t + 1 < TSTEPS) {
                sm.hbuf[1][buf ^ 1][rank][wloc][lane] = hreg;
                __syncwarp();
                asm volatile("fence.proxy.async.shared::cta;" ::: "memory");
                if (lane < 8) {
                    const unsigned off = hoff +
                        (unsigned)(8192 + (buf ^ 1) * 4096 + rank * 512 + wloc * 128);
                    asm volatile(
                        "cp.async.bulk.shared::cluster.shared::cta.mbarrier::complete_tx::bytes "
                        "[%0], [%1], %2, [%3];"
                        :: "r"(peer + off), "r"(base + off), "r"(128u),
                           "r"(peer + mboff + (unsigned)(16 + (buf ^ 1) * 8)) : "memory");
                }
            }
            if (rank == 0) {
                float prod = (lane < LDIM) ? hreg * xl_reg : 0.f;
#pragma unroll
                for (int o = 16; o; o >>= 1)
                    prod += __shfl_xor_sync(0xffffffffu, prod, o);
                if (lane == 0) out[(size_t)(B0 + warp) * TSTEPS + t] = prod;
                if (lane < LDIM)
                    xl_reg = xl[(size_t)(B0 + warp) * TSTEPS * LDIM +
                                (size_t)tn * LDIM + lane];
            }
        }
    }

    cluster.sync();   // clean distributed exit
}

extern "C" void kernel_launch(void* const* d_in, const int* in_sizes, int n_in,
                              void* d_out, int out_size) {
    (void)in_sizes; (void)n_in; (void)out_size;
    const float* xg     = (const float*)d_in[0];  // input_gru   [128,2048,32]
    const float* xl     = (const float*)d_in[1];  // input_linear[128,2048,16]
    const float* h0     = (const float*)d_in[2];  // init_hidden [128,256]
    const float* Wih    = (const float*)d_in[3];  // [768,32]
    const float* Whh    = (const float*)d_in[4];  // [768,256]
    const float* bias   = (const float*)d_in[5];  // [768]
    const float* bias_n = (const float*)d_in[6];  // [256]
    float* out = (float*)d_out;                   // [128,2048,1]

    cudaFuncSetAttribute(gru_persistent_kernel,
                         cudaFuncAttributeMaxDynamicSharedMemorySize, SMEM_BYTES);

    gru_persistent_kernel<<<dim3(BATCH), dim3(TB), SMEM_BYTES>>>(
        xg, xl, h0, Wih, Whh, bias, bias_n, out);
}